// round 14
// baseline (speedup 1.0000x reference)
#include <cuda_runtime.h>
#include <cuda_bf16.h>
#include <cstdint>

#define EMB        128
#define HEADS      4
#define MAX_NODES  50000
#define MAX_EDGES  600000

// ---------------- scratch (static device globals; no allocation) -------------
__device__ float g_qkv[3 * MAX_NODES * EMB];            // Q | K | V  (76.8 MB)
__device__ float g_norm[MAX_NODES * HEADS];             // segment softmax denom
__device__ __nv_bfloat16 g_wt_hi[3 * EMB * EMB];        // W^T split, hi
__device__ __nv_bfloat16 g_wt_lo[3 * EMB * EMB];        // W^T split, lo
__device__ __nv_bfloat16 g_a_hi[MAX_NODES * EMB];       // embeds split, hi (12.8 MB)
__device__ __nv_bfloat16 g_a_lo[MAX_NODES * EMB];       // embeds split, lo

// ---------------- smem geometry (gemm): XOR-swizzled 256B rows ---------------
#define TILE32K  32768
#define SM_A_HI  0
#define SM_A_LO  TILE32K
#define SM_B     (2 * TILE32K)
#define SM_TOTAL (3 * TILE32K)          // 98304 B -> 2 CTAs/SM

__device__ __forceinline__ uint32_t smem_u32(const void* p) {
    uint32_t a;
    asm("{ .reg .u64 t; cvta.to.shared.u64 t, %1; cvt.u32.u64 %0, t; }"
        : "=r"(a) : "l"(p));
    return a;
}
// row-major [128][256B] tile, swizzled: 16B slot rotated by row within 8-row group
__device__ __forceinline__ uint32_t swz(int row, int colb) {
    return (uint32_t)row * 256u + ((uint32_t)colb ^ (((uint32_t)row & 7u) << 4));
}

// ---------------- kernel 0: zero out + norm ---------------------------------
__global__ void zero_kernel(float* __restrict__ out, int n_out, int n_norm) {
    int i = blockIdx.x * blockDim.x + threadIdx.x;
    int stride = gridDim.x * blockDim.x;
    for (int idx = i; idx < n_out; idx += stride) out[idx] = 0.0f;
    for (int idx = i; idx < n_norm; idx += stride) g_norm[idx] = 0.0f;
}

// ---------------- kernel 0b: split weights (transposed) ----------------------
__global__ void prep_weights(const float* __restrict__ qW,
                             const float* __restrict__ kW,
                             const float* __restrict__ vW) {
    int t = blockIdx.x * blockDim.x + threadIdx.x;
    if (t >= 3 * EMB * EMB) return;
    int w   = t / (EMB * EMB);
    int rem = t - w * (EMB * EMB);
    int j   = rem >> 7;
    int k   = rem & 127;
    const float* W = (w == 0) ? qW : (w == 1) ? kW : vW;
    float x = W[k * EMB + j];
    __nv_bfloat16 hi = __float2bfloat16(x);
    __nv_bfloat16 lo = __float2bfloat16(x - __bfloat162float(hi));
    g_wt_hi[t] = hi;
    g_wt_lo[t] = lo;
}

// ---------------- kernel 0c: split embeds to bf16 hi/lo (once) ---------------
__global__ void prep_a(const float* __restrict__ A, int N) {
    int idx = blockIdx.x * blockDim.x + threadIdx.x;     // one float4 each
    int total = N * (EMB / 4);
    if (idx >= total) return;
    float4 f = reinterpret_cast<const float4*>(A)[idx];
    float x[4] = {f.x, f.y, f.z, f.w};
    __nv_bfloat16 hi[4], lo[4];
#pragma unroll
    for (int p = 0; p < 4; p++) {
        hi[p] = __float2bfloat16(x[p]);
        lo[p] = __float2bfloat16(x[p] - __bfloat162float(hi[p]));
    }
    reinterpret_cast<uint2*>(g_a_hi)[idx] =
        make_uint2((uint32_t)__bfloat16_as_ushort(hi[0]) | ((uint32_t)__bfloat16_as_ushort(hi[1]) << 16),
                   (uint32_t)__bfloat16_as_ushort(hi[2]) | ((uint32_t)__bfloat16_as_ushort(hi[3]) << 16));
    reinterpret_cast<uint2*>(g_a_lo)[idx] =
        make_uint2((uint32_t)__bfloat16_as_ushort(lo[0]) | ((uint32_t)__bfloat16_as_ushort(lo[1]) << 16),
                   (uint32_t)__bfloat16_as_ushort(lo[2]) | ((uint32_t)__bfloat16_as_ushort(lo[3]) << 16));
}

// ---------------- one bf16 MMA pass over the K dimension ---------------------
__device__ __forceinline__ void mma_pass(uint32_t ua, uint32_t ub,
                                         int wm, int wn, int g8, int r8,
                                         float acc[16][4]) {
#pragma unroll
    for (int ks = 0; ks < 8; ks++) {
        int k0 = ks * 16;
        uint32_t a[2][4];
#pragma unroll
        for (int i = 0; i < 2; i++) {
            int row  = wm + i * 16 + (g8 & 1) * 8 + r8;
            int colb = (k0 + (g8 >> 1) * 8) * 2;
            uint32_t addr = ua + swz(row, colb);
            asm volatile(
                "ldmatrix.sync.aligned.m8n8.x4.shared.b16 {%0,%1,%2,%3}, [%4];"
                : "=r"(a[i][0]), "=r"(a[i][1]), "=r"(a[i][2]), "=r"(a[i][3])
                : "r"(addr));
        }
        uint32_t b[8][2];
#pragma unroll
        for (int j2 = 0; j2 < 4; j2++) {
            int row  = wn + j2 * 16 + (g8 >> 1) * 8 + r8;
            int colb = (k0 + (g8 & 1) * 8) * 2;
            uint32_t addr = ub + swz(row, colb);
            uint32_t x0, x1, x2, x3;
            asm volatile(
                "ldmatrix.sync.aligned.m8n8.x4.shared.b16 {%0,%1,%2,%3}, [%4];"
                : "=r"(x0), "=r"(x1), "=r"(x2), "=r"(x3)
                : "r"(addr));
            b[j2*2    ][0] = x0; b[j2*2    ][1] = x1;
            b[j2*2 + 1][0] = x2; b[j2*2 + 1][1] = x3;
        }
#pragma unroll
        for (int i = 0; i < 2; i++)
#pragma unroll
            for (int j = 0; j < 8; j++) {
                int t = i * 8 + j;
                asm volatile(
                    "mma.sync.aligned.m16n8k16.row.col.f32.bf16.bf16.f32 "
                    "{%0,%1,%2,%3}, {%4,%5,%6,%7}, {%8,%9}, {%0,%1,%2,%3};"
                    : "+f"(acc[t][0]), "+f"(acc[t][1]),
                      "+f"(acc[t][2]), "+f"(acc[t][3])
                    : "r"(a[i][0]), "r"(a[i][1]), "r"(a[i][2]), "r"(a[i][3]),
                      "r"(b[j][0]), "r"(b[j][1]));
            }
    }
}

// ---------------- kernel 1: QKV projection (bf16x3 HMMA, 96KB smem) ----------
// grid (3, mtiles).  Passes: Ah.Bh, Al.Bh with B=Bh; reload B<-Bl; Ah.Bl.
__global__ __launch_bounds__(256, 2) void qkv_gemm_mma(int N)
{
    extern __shared__ char smem[];
    uint32_t sb = smem_u32(smem);

    int tid  = threadIdx.x;
    int warp = tid >> 5;
    int lane = tid & 31;
    int w    = blockIdx.x;
    int m0   = blockIdx.y * 128;

    // ---- stage A hi/lo from pre-split global (copy only) --------------------
#pragma unroll
    for (int i = 0; i < 8; i++) {
        int f     = tid + i * 256;          // 0..2047
        int row   = f >> 4;
        int colu4 = f & 15;
        int gm    = m0 + row;
        uint4 vh = make_uint4(0u,0u,0u,0u), vl = make_uint4(0u,0u,0u,0u);
        if (gm < N) {
            vh = *reinterpret_cast<const uint4*>(g_a_hi + (size_t)gm * EMB + colu4 * 8);
            vl = *reinterpret_cast<const uint4*>(g_a_lo + (size_t)gm * EMB + colu4 * 8);
        }
        uint32_t off = swz(row, colu4 * 16);
        *reinterpret_cast<uint4*>(smem + SM_A_HI + off) = vh;
        *reinterpret_cast<uint4*>(smem + SM_A_LO + off) = vl;
    }
    // ---- stage B = W^T hi -----------------------------------------------------
    const __nv_bfloat16* wt_hi = g_wt_hi + (size_t)w * EMB * EMB;
    const __nv_bfloat16* wt_lo = g_wt_lo + (size_t)w * EMB * EMB;
#pragma unroll
    for (int i = 0; i < 8; i++) {
        int f     = tid + i * 256;
        int row   = f >> 4;
        int colu4 = f & 15;
        *reinterpret_cast<uint4*>(smem + SM_B + swz(row, colu4 * 16)) =
            *reinterpret_cast<const uint4*>(wt_hi + (size_t)row * EMB + colu4 * 8);
    }
    __syncthreads();

    const int wm = (warp & 3) * 32;
    const int wn = (warp >> 2) * 64;
    const int g8 = lane >> 3;
    const int r8 = lane & 7;

    float acc[16][4];
#pragma unroll
    for (int t = 0; t < 16; t++)
#pragma unroll
        for (int q = 0; q < 4; q++) acc[t][q] = 0.0f;

    mma_pass(sb + SM_A_HI, sb + SM_B, wm, wn, g8, r8, acc);   // Ah.Bh
    mma_pass(sb + SM_A_LO, sb + SM_B, wm, wn, g8, r8, acc);   // Al.Bh
    __syncthreads();
    // reload B <- W^T lo
#pragma unroll
    for (int i = 0; i < 8; i++) {
        int f     = tid + i * 256;
        int row   = f >> 4;
        int colu4 = f & 15;
        *reinterpret_cast<uint4*>(smem + SM_B + swz(row, colu4 * 16)) =
            *reinterpret_cast<const uint4*>(wt_lo + (size_t)row * EMB + colu4 * 8);
    }
    __syncthreads();
    mma_pass(sb + SM_A_HI, sb + SM_B, wm, wn, g8, r8, acc);   // Ah.Bl

    // ---- epilogue -----------------------------------------------------------
    {
        float* C = g_qkv + (size_t)w * (size_t)N * EMB;
        int qrow = lane >> 2;
        int qcol = (lane & 3) * 2;
#pragma unroll
        for (int t = 0; t < 16; t++) {
            int i = t >> 3, j = t & 7;
            int gr = m0 + wm + i*16 + qrow;
            int gc = wn + j*8 + qcol;
            if (gr < N)
                *reinterpret_cast<float2*>(C + (size_t)gr * EMB + gc) =
                    make_float2(acc[t][0], acc[t][1]);
            int gr2 = gr + 8;
            if (gr2 < N)
                *reinterpret_cast<float2*>(C + (size_t)gr2 * EMB + gc) =
                    make_float2(acc[t][2], acc[t][3]);
        }
    }
}

// ---------------- kernel 2: fused edge pass, 4 edges per warp ----------------
__global__ __launch_bounds__(256) void edge_fused(
    const int* __restrict__ rows, const int* __restrict__ cols,
    float* __restrict__ out, int E, int N)
{
    int quad = (blockIdx.x * blockDim.x + threadIdx.x) >> 5;
    int lane = threadIdx.x & 31;
    int e0 = quad * 4;
    if (e0 >= E) return;
    int nrem = E - e0;                      // >= 1

    int r0, r1, r2, r3, c0, c1, c2, c3;
    if (nrem >= 4) {
        int4 rr = *reinterpret_cast<const int4*>(rows + e0);
        int4 cc = *reinterpret_cast<const int4*>(cols + e0);
        r0 = rr.x; r1 = rr.y; r2 = rr.z; r3 = rr.w;
        c0 = cc.x; c1 = cc.y; c2 = cc.z; c3 = cc.w;
    } else {
        r0 = rows[e0];               c0 = cols[e0];
        r1 = rows[e0 + min(1, nrem - 1)]; c1 = cols[e0 + min(1, nrem - 1)];
        r2 = rows[e0 + min(2, nrem - 1)]; c2 = cols[e0 + min(2, nrem - 1)];
        r3 = rows[e0 + min(3, nrem - 1)]; c3 = cols[e0 + min(3, nrem - 1)];
    }

    const float* Q = g_qkv;
    const float* K = g_qkv + (size_t)N * EMB;
    const float* V = g_qkv + 2 * (size_t)N * EMB;
    int d = lane * 4;

    // twelve independent 16B gathers, issued before any consumer
    float4 q0 = *reinterpret_cast<const float4*>(Q + (size_t)r0 * EMB + d);
    float4 q1 = *reinterpret_cast<const float4*>(Q + (size_t)r1 * EMB + d);
    float4 q2 = *reinterpret_cast<const float4*>(Q + (size_t)r2 * EMB + d);
    float4 q3 = *reinterpret_cast<const float4*>(Q + (size_t)r3 * EMB + d);
    float4 k0 = *reinterpret_cast<const float4*>(K + (size_t)c0 * EMB + d);
    float4 k1 = *reinterpret_cast<const float4*>(K + (size_t)c1 * EMB + d);
    float4 k2 = *reinterpret_cast<const float4*>(K + (size_t)c2 * EMB + d);
    float4 k3 = *reinterpret_cast<const float4*>(K + (size_t)c3 * EMB + d);
    float4 v0 = *reinterpret_cast<const float4*>(V + (size_t)c0 * EMB + d);
    float4 v1 = *reinterpret_cast<const float4*>(V + (size_t)c1 * EMB + d);
    float4 v2 = *reinterpret_cast<const float4*>(V + (size_t)c2 * EMB + d);
    float4 v3 = *reinterpret_cast<const float4*>(V + (size_t)c3 * EMB + d);

    float p0 = q0.x*k0.x; p0 = fmaf(q0.y,k0.y,p0); p0 = fmaf(q0.z,k0.z,p0); p0 = fmaf(q0.w,k0.w,p0);
    float p1 = q1.x*k1.x; p1 = fmaf(q1.y,k1.y,p1); p1 = fmaf(q1.z,k1.z,p1); p1 = fmaf(q1.w,k1.w,p1);
    float p2 = q2.x*k2.x; p2 = fmaf(q2.y,k2.y,p2); p2 = fmaf(q2.z,k2.z,p2); p2 = fmaf(q2.w,k2.w,p2);
    float p3 = q3.x*k3.x; p3 = fmaf(q3.y,k3.y,p3); p3 = fmaf(q3.z,k3.z,p3); p3 = fmaf(q3.w,k3.w,p3);

    p0 += __shfl_xor_sync(0xffffffffu, p0, 1);
    p1 += __shfl_xor_sync(0xffffffffu, p1, 1);
    p2 += __shfl_xor_sync(0xffffffffu, p2, 1);
    p3 += __shfl_xor_sync(0xffffffffu, p3, 1);
    p0 += __shfl_xor_sync(0xffffffffu, p0, 2);
    p1 += __shfl_xor_sync(0xffffffffu, p1, 2);
    p2 += __shfl_xor_sync(0xffffffffu, p2, 2);
    p3 += __shfl_xor_sync(0xffffffffu, p3, 2);
    p0 += __shfl_xor_sync(0xffffffffu, p0, 4);
    p1 += __shfl_xor_sync(0xffffffffu, p1, 4);
    p2 += __shfl_xor_sync(0xffffffffu, p2, 4);
    p3 += __shfl_xor_sync(0xffffffffu, p3, 4);

    float a0 = __expf(fminf(fmaxf(p0, -10.0f), 10.0f));
    float a1 = __expf(fminf(fmaxf(p1, -10.0f), 10.0f));
    float a2 = __expf(fminf(fmaxf(p2, -10.0f), 10.0f));
    float a3 = __expf(fminf(fmaxf(p3, -10.0f), 10.0f));

    int sub = lane & 7;
    int h   = lane >> 3;
    if (sub < 4 && (e0 + sub) < E) {
        float av = (sub == 0) ? a0 : (sub == 1) ? a1 : (sub == 2) ? a2 : a3;
        int   rv = (sub == 0) ? r0 : (sub == 1) ? r1 : (sub == 2) ? r2 : r3;
        atomicAdd(&g_norm[rv * HEADS + h], av);
    }

    float* op0 = out + (size_t)r0 * EMB + d;
    asm volatile("red.global.add.v4.f32 [%0], {%1, %2, %3, %4};"
                 :: "l"(op0), "f"(a0*v0.x), "f"(a0*v0.y), "f"(a0*v0.z), "f"(a0*v0.w) : "memory");
    if (nrem > 1) {
        float* op1 = out + (size_t)r1 * EMB + d;
        asm volatile("red.global.add.v4.f32 [%0], {%1, %2, %3, %4};"
                     :: "l"(op1), "f"(a1*v1.x), "f"(a1*v1.y), "f"(a1*v1.z), "f"(a1*v1.w) : "memory");
    }
    if (nrem > 2) {
        float* op2 = out + (size_t)r2 * EMB + d;
        asm volatile("red.global.add.v4.f32 [%0], {%1, %2, %3, %4};"
                     :: "l"(op2), "f"(a2*v2.x), "f"(a2*v2.y), "f"(a2*v2.z), "f"(a2*v2.w) : "memory");
    }
    if (nrem > 3) {
        float* op3 = out + (size_t)r3 * EMB + d;
        asm volatile("red.global.add.v4.f32 [%0], {%1, %2, %3, %4};"
                     :: "l"(op3), "f"(a3*v3.x), "f"(a3*v3.y), "f"(a3*v3.z), "f"(a3*v3.w) : "memory");
    }
}

// ---------------- kernel 3: deferred normalization ---------------------------
__global__ __launch_bounds__(256) void scale_kernel(float* __restrict__ out, int N)
{
    int idx = blockIdx.x * blockDim.x + threadIdx.x;
    int total = N * (EMB / 4);
    if (idx >= total) return;
    int n  = idx >> 5;
    int d4 = idx & 31;
    int h  = d4 >> 3;
    float inv = 1.0f / (g_norm[n * HEADS + h] + 1e-8f);
    float4* p = reinterpret_cast<float4*>(out) + idx;
    float4 vv = *p;
    vv.x *= inv; vv.y *= inv; vv.z *= inv; vv.w *= inv;
    *p = vv;
}

// ---------------- launch -----------------------------------------------------
extern "C" void kernel_launch(void* const* d_in, const int* in_sizes, int n_in,
                              void* d_out, int out_size)
{
    const float* embeds = (const float*)d_in[0];
    const float* qW     = (const float*)d_in[1];
    const float* kW     = (const float*)d_in[2];
    const float* vW     = (const float*)d_in[3];
    const int*   rows   = (const int*)d_in[4];
    const int*   cols   = (const int*)d_in[5];

    int N = in_sizes[0] / EMB;
    int E = in_sizes[4];
    float* out = (float*)d_out;

    static bool attr_set = false;
    if (!attr_set) {
        cudaFuncSetAttribute(qkv_gemm_mma,
                             cudaFuncAttributeMaxDynamicSharedMemorySize, SM_TOTAL);
        attr_set = true;
    }

    zero_kernel<<<2048, 256>>>(out, N * EMB, N * HEADS);
    prep_weights<<<(3 * EMB * EMB + 255) / 256, 256>>>(qW, kW, vW);
    prep_a<<<(N * (EMB / 4) + 255) / 256, 256>>>(embeds, N);

    int mtiles = (N + 127) / 128;
    qkv_gemm_mma<<<dim3(3, mtiles), 256, SM_TOTAL>>>(N);

    int quads   = (E + 3) / 4;
    int eblocks = (quads + 7) / 8;      // 8 warps (quads) per 256-thread block
    edge_fused<<<eblocks, 256>>>(rows, cols, out, E, N);

    scale_kernel<<<(N * (EMB / 4) + 255) / 256, 256>>>(out, N);
}

// round 15
// speedup vs baseline: 1.0788x; 1.0788x over previous
#include <cuda_runtime.h>
#include <cuda_bf16.h>
#include <cstdint>

#define EMB        128
#define HEADS      4
#define MAX_NODES  50000
#define MAX_EDGES  600000

// ---------------- scratch (static device globals; no allocation) -------------
__device__ float g_qkv[3 * MAX_NODES * EMB];            // Q | K | V  (76.8 MB)
__device__ float g_norm[MAX_NODES * HEADS];             // segment softmax denom
__device__ __nv_bfloat16 g_wt_hi[3 * EMB * EMB];        // W^T split, hi
__device__ __nv_bfloat16 g_wt_lo[3 * EMB * EMB];        // W^T split, lo
__device__ __nv_bfloat16 g_a_hi[MAX_NODES * EMB];       // embeds split, hi
__device__ __nv_bfloat16 g_a_lo[MAX_NODES * EMB];       // embeds split, lo

// ---------------- smem geometry (gemm): XOR-swizzled 256B rows ---------------
#define TILE32K  32768
#define SM_A_HI  0
#define SM_A_LO  TILE32K
#define SM_B     (2 * TILE32K)
#define SM_TOTAL (3 * TILE32K)          // 98304 B -> 2 CTAs/SM

__device__ __forceinline__ uint32_t smem_u32(const void* p) {
    uint32_t a;
    asm("{ .reg .u64 t; cvta.to.shared.u64 t, %1; cvt.u32.u64 %0, t; }"
        : "=r"(a) : "l"(p));
    return a;
}
__device__ __forceinline__ uint32_t swz(int row, int colb) {
    return (uint32_t)row * 256u + ((uint32_t)colb ^ (((uint32_t)row & 7u) << 4));
}
__device__ __forceinline__ void cp16(uint32_t dst, const void* src, int sz) {
    asm volatile("cp.async.ca.shared.global [%0], [%1], 16, %2;"
                 :: "r"(dst), "l"(__cvta_generic_to_global(src)), "r"(sz));
}
__device__ __forceinline__ void cp_commit_wait() {
    asm volatile("cp.async.commit_group;");
    asm volatile("cp.async.wait_group 0;" ::: "memory");
}

// ---------------- kernel 0: zero out + norm ---------------------------------
__global__ void zero_kernel(float* __restrict__ out, int n_out, int n_norm) {
    int i = blockIdx.x * blockDim.x + threadIdx.x;
    int stride = gridDim.x * blockDim.x;
    for (int idx = i; idx < n_out; idx += stride) out[idx] = 0.0f;
    for (int idx = i; idx < n_norm; idx += stride) g_norm[idx] = 0.0f;
}

// ---------------- kernel 0b: split weights (transposed) ----------------------
__global__ void prep_weights(const float* __restrict__ qW,
                             const float* __restrict__ kW,
                             const float* __restrict__ vW) {
    int t = blockIdx.x * blockDim.x + threadIdx.x;
    if (t >= 3 * EMB * EMB) return;
    int w   = t / (EMB * EMB);
    int rem = t - w * (EMB * EMB);
    int j   = rem >> 7;
    int k   = rem & 127;
    const float* W = (w == 0) ? qW : (w == 1) ? kW : vW;
    float x = W[k * EMB + j];
    __nv_bfloat16 hi = __float2bfloat16(x);
    __nv_bfloat16 lo = __float2bfloat16(x - __bfloat162float(hi));
    g_wt_hi[t] = hi;
    g_wt_lo[t] = lo;
}

// ---------------- kernel 0c: split embeds to bf16 hi/lo ----------------------
__global__ void prep_a(const float* __restrict__ A, int N) {
    int idx = blockIdx.x * blockDim.x + threadIdx.x;
    int total = N * (EMB / 4);
    if (idx >= total) return;
    float4 f = reinterpret_cast<const float4*>(A)[idx];
    float x[4] = {f.x, f.y, f.z, f.w};
    __nv_bfloat16 hi[4], lo[4];
#pragma unroll
    for (int p = 0; p < 4; p++) {
        hi[p] = __float2bfloat16(x[p]);
        lo[p] = __float2bfloat16(x[p] - __bfloat162float(hi[p]));
    }
    reinterpret_cast<uint2*>(g_a_hi)[idx] =
        make_uint2((uint32_t)__bfloat16_as_ushort(hi[0]) | ((uint32_t)__bfloat16_as_ushort(hi[1]) << 16),
                   (uint32_t)__bfloat16_as_ushort(hi[2]) | ((uint32_t)__bfloat16_as_ushort(hi[3]) << 16));
    reinterpret_cast<uint2*>(g_a_lo)[idx] =
        make_uint2((uint32_t)__bfloat16_as_ushort(lo[0]) | ((uint32_t)__bfloat16_as_ushort(lo[1]) << 16),
                   (uint32_t)__bfloat16_as_ushort(lo[2]) | ((uint32_t)__bfloat16_as_ushort(lo[3]) << 16));
}

// ---------------- one bf16 MMA pass (B frags in two halves of 4) -------------
__device__ __forceinline__ void mma_pass(uint32_t ua, uint32_t ub,
                                         int wm, int wn, int g8, int r8,
                                         float acc[16][4]) {
#pragma unroll
    for (int ks = 0; ks < 8; ks++) {
        int k0 = ks * 16;
        uint32_t a[2][4];
#pragma unroll
        for (int i = 0; i < 2; i++) {
            int row  = wm + i * 16 + (g8 & 1) * 8 + r8;
            int colb = (k0 + (g8 >> 1) * 8) * 2;
            uint32_t addr = ua + swz(row, colb);
            asm volatile(
                "ldmatrix.sync.aligned.m8n8.x4.shared.b16 {%0,%1,%2,%3}, [%4];"
                : "=r"(a[i][0]), "=r"(a[i][1]), "=r"(a[i][2]), "=r"(a[i][3])
                : "r"(addr));
        }
#pragma unroll
        for (int bh = 0; bh < 2; bh++) {          // half of the n range
            uint32_t b[4][2];
#pragma unroll
            for (int q = 0; q < 2; q++) {
                int j2   = bh * 2 + q;
                int row  = wn + j2 * 16 + (g8 >> 1) * 8 + r8;
                int colb = (k0 + (g8 & 1) * 8) * 2;
                uint32_t addr = ub + swz(row, colb);
                uint32_t x0, x1, x2, x3;
                asm volatile(
                    "ldmatrix.sync.aligned.m8n8.x4.shared.b16 {%0,%1,%2,%3}, [%4];"
                    : "=r"(x0), "=r"(x1), "=r"(x2), "=r"(x3)
                    : "r"(addr));
                b[q*2    ][0] = x0; b[q*2    ][1] = x1;
                b[q*2 + 1][0] = x2; b[q*2 + 1][1] = x3;
            }
#pragma unroll
            for (int i = 0; i < 2; i++)
#pragma unroll
                for (int jj = 0; jj < 4; jj++) {
                    int t = i * 8 + bh * 4 + jj;
                    asm volatile(
                        "mma.sync.aligned.m16n8k16.row.col.f32.bf16.bf16.f32 "
                        "{%0,%1,%2,%3}, {%4,%5,%6,%7}, {%8,%9}, {%0,%1,%2,%3};"
                        : "+f"(acc[t][0]), "+f"(acc[t][1]),
                          "+f"(acc[t][2]), "+f"(acc[t][3])
                        : "r"(a[i][0]), "r"(a[i][1]), "r"(a[i][2]), "r"(a[i][3]),
                          "r"(b[jj][0]), "r"(b[jj][1]));
                }
        }
    }
}

// ---------------- kernel 1: QKV projection (bf16x3 HMMA) ---------------------
__global__ __launch_bounds__(256, 2) void qkv_gemm_mma(int N)
{
    extern __shared__ char smem[];
    uint32_t sb = smem_u32(smem);

    int tid  = threadIdx.x;
    int warp = tid >> 5;
    int lane = tid & 31;
    int w    = blockIdx.x;
    int m0   = blockIdx.y * 128;

    const __nv_bfloat16* wt_hi = g_wt_hi + (size_t)w * EMB * EMB;
    const __nv_bfloat16* wt_lo = g_wt_lo + (size_t)w * EMB * EMB;

    // ---- stage A hi/lo + B hi via cp.async ----------------------------------
#pragma unroll
    for (int i = 0; i < 8; i++) {
        int f     = tid + i * 256;          // 0..2047
        int row   = f >> 4;
        int colu4 = f & 15;
        int gm    = m0 + row;
        int sz    = (gm < N) ? 16 : 0;
        uint32_t off = swz(row, colu4 * 16);
        cp16(sb + SM_A_HI + off, g_a_hi + (size_t)gm * EMB + colu4 * 8, sz);
        cp16(sb + SM_A_LO + off, g_a_lo + (size_t)gm * EMB + colu4 * 8, sz);
        cp16(sb + SM_B    + off, wt_hi   + (size_t)row * EMB + colu4 * 8, 16);
    }
    cp_commit_wait();
    __syncthreads();

    const int wm = (warp & 3) * 32;
    const int wn = (warp >> 2) * 64;
    const int g8 = lane >> 3;
    const int r8 = lane & 7;

    float acc[16][4];
#pragma unroll
    for (int t = 0; t < 16; t++)
#pragma unroll
        for (int q = 0; q < 4; q++) acc[t][q] = 0.0f;

    mma_pass(sb + SM_A_HI, sb + SM_B, wm, wn, g8, r8, acc);   // Ah.Bh
    mma_pass(sb + SM_A_LO, sb + SM_B, wm, wn, g8, r8, acc);   // Al.Bh
    __syncthreads();
#pragma unroll
    for (int i = 0; i < 8; i++) {
        int f     = tid + i * 256;
        int row   = f >> 4;
        int colu4 = f & 15;
        cp16(sb + SM_B + swz(row, colu4 * 16),
             wt_lo + (size_t)row * EMB + colu4 * 8, 16);
    }
    cp_commit_wait();
    __syncthreads();
    mma_pass(sb + SM_A_HI, sb + SM_B, wm, wn, g8, r8, acc);   // Ah.Bl

    // ---- epilogue -----------------------------------------------------------
    {
        float* C = g_qkv + (size_t)w * (size_t)N * EMB;
        int qrow = lane >> 2;
        int qcol = (lane & 3) * 2;
#pragma unroll
        for (int t = 0; t < 16; t++) {
            int i = t >> 3, j = t & 7;
            int gr = m0 + wm + i*16 + qrow;
            int gc = wn + j*8 + qcol;
            if (gr < N)
                *reinterpret_cast<float2*>(C + (size_t)gr * EMB + gc) =
                    make_float2(acc[t][0], acc[t][1]);
            int gr2 = gr + 8;
            if (gr2 < N)
                *reinterpret_cast<float2*>(C + (size_t)gr2 * EMB + gc) =
                    make_float2(acc[t][2], acc[t][3]);
        }
    }
}

// ---------------- kernel 2: fused edge pass, 2 edges per warp ----------------
__global__ __launch_bounds__(256) void edge_fused(
    const int* __restrict__ rows, const int* __restrict__ cols,
    float* __restrict__ out, int E, int N)
{
    int pair = (blockIdx.x * blockDim.x + threadIdx.x) >> 5;
    int lane = threadIdx.x & 31;
    int e0 = pair * 2;
    if (e0 >= E) return;
    bool has1 = (e0 + 1) < E;

    int2 rr = *reinterpret_cast<const int2*>(rows + e0);
    int2 cc = *reinterpret_cast<const int2*>(cols + e0);
    int r0 = rr.x, c0 = cc.x;
    int r1 = has1 ? rr.y : rr.x;
    int c1 = has1 ? cc.y : cc.x;

    const float* Q = g_qkv;
    const float* K = g_qkv + (size_t)N * EMB;
    const float* V = g_qkv + 2 * (size_t)N * EMB;
    int d = lane * 4;

    float4 q0 = *reinterpret_cast<const float4*>(Q + (size_t)r0 * EMB + d);
    float4 k0 = *reinterpret_cast<const float4*>(K + (size_t)c0 * EMB + d);
    float4 v0 = *reinterpret_cast<const float4*>(V + (size_t)c0 * EMB + d);
    float4 q1 = *reinterpret_cast<const float4*>(Q + (size_t)r1 * EMB + d);
    float4 k1 = *reinterpret_cast<const float4*>(K + (size_t)c1 * EMB + d);
    float4 v1 = *reinterpret_cast<const float4*>(V + (size_t)c1 * EMB + d);

    float p0 = q0.x * k0.x;
    p0 = fmaf(q0.y, k0.y, p0);
    p0 = fmaf(q0.z, k0.z, p0);
    p0 = fmaf(q0.w, k0.w, p0);
    float p1 = q1.x * k1.x;
    p1 = fmaf(q1.y, k1.y, p1);
    p1 = fmaf(q1.z, k1.z, p1);
    p1 = fmaf(q1.w, k1.w, p1);

    p0 += __shfl_xor_sync(0xffffffffu, p0, 1);
    p1 += __shfl_xor_sync(0xffffffffu, p1, 1);
    p0 += __shfl_xor_sync(0xffffffffu, p0, 2);
    p1 += __shfl_xor_sync(0xffffffffu, p1, 2);
    p0 += __shfl_xor_sync(0xffffffffu, p0, 4);
    p1 += __shfl_xor_sync(0xffffffffu, p1, 4);

    float a0 = __expf(fminf(fmaxf(p0, -10.0f), 10.0f));
    float a1 = __expf(fminf(fmaxf(p1, -10.0f), 10.0f));

    int sub = lane & 7;
    int h   = lane >> 3;
    if (sub == 0)
        atomicAdd(&g_norm[r0 * HEADS + h], a0);
    else if (sub == 1 && has1)
        atomicAdd(&g_norm[r1 * HEADS + h], a1);

    float* op0 = out + (size_t)r0 * EMB + d;
    asm volatile("red.global.add.v4.f32 [%0], {%1, %2, %3, %4};"
                 :: "l"(op0), "f"(a0 * v0.x), "f"(a0 * v0.y),
                    "f"(a0 * v0.z), "f"(a0 * v0.w)
                 : "memory");
    if (has1) {
        float* op1 = out + (size_t)r1 * EMB + d;
        asm volatile("red.global.add.v4.f32 [%0], {%1, %2, %3, %4};"
                     :: "l"(op1), "f"(a1 * v1.x), "f"(a1 * v1.y),
                        "f"(a1 * v1.z), "f"(a1 * v1.w)
                     : "memory");
    }
}

// ---------------- kernel 3: deferred normalization ---------------------------
__global__ __launch_bounds__(256) void scale_kernel(float* __restrict__ out, int N)
{
    int idx = blockIdx.x * blockDim.x + threadIdx.x;
    int total = N * (EMB / 4);
    if (idx >= total) return;
    int n  = idx >> 5;
    int d4 = idx & 31;
    int h  = d4 >> 3;
    float inv = 1.0f / (g_norm[n * HEADS + h] + 1e-8f);
    float4* p = reinterpret_cast<float4*>(out) + idx;
    float4 vv = *p;
    vv.x *= inv; vv.y *= inv; vv.z *= inv; vv.w *= inv;
    *p = vv;
}

// ---------------- launch -----------------------------------------------------
extern "C" void kernel_launch(void* const* d_in, const int* in_sizes, int n_in,
                              void* d_out, int out_size)
{
    const float* embeds = (const float*)d_in[0];
    const float* qW     = (const float*)d_in[1];
    const float* kW     = (const float*)d_in[2];
    const float* vW     = (const float*)d_in[3];
    const int*   rows   = (const int*)d_in[4];
    const int*   cols   = (const int*)d_in[5];

    int N = in_sizes[0] / EMB;
    int E = in_sizes[4];
    float* out = (float*)d_out;

    static bool attr_set = false;
    if (!attr_set) {
        cudaFuncSetAttribute(qkv_gemm_mma,
                             cudaFuncAttributeMaxDynamicSharedMemorySize, SM_TOTAL);
        attr_set = true;
    }

    zero_kernel<<<2048, 256>>>(out, N * EMB, N * HEADS);
    prep_weights<<<(3 * EMB * EMB + 255) / 256, 256>>>(qW, kW, vW);
    prep_a<<<(N * (EMB / 4) + 255) / 256, 256>>>(embeds, N);

    int mtiles = (N + 127) / 128;
    qkv_gemm_mma<<<dim3(3, mtiles), 256, SM_TOTAL>>>(N);

    int pairs   = (E + 1) / 2;
    int eblocks = (pairs + 7) / 8;
    edge_fused<<<eblocks, 256>>>(rows, cols, out, E, N);

    scale_kernel<<<(N * (EMB / 4) + 255) / 256, 256>>>(out, N);
}